// round 3
// baseline (speedup 1.0000x reference)
#include <cuda_runtime.h>

// Problem constants (fixed by the reference)
#define Bp    4
#define Tp    512
#define Kp    256
#define DENC  256
#define DKp   256
#define UN    128
#define TT    8     // timesteps per block in the main kernel

// Scratch: kkT[b][u][k] = (knowledge[b] @ W2 + b2) transposed to [U][K]
__device__ float g_kkT[Bp * UN * Kp];   // 512 KB

// ---------------------------------------------------------------------------
// Pre-kernel: kkT[b][u][k] = sum_d knowledge[b,k,d] * W2[d,u] + b2[u]
// grid = B * (K/8) = 128 blocks, 256 threads.
// ---------------------------------------------------------------------------
__global__ void __launch_bounds__(256) kk_pre_kernel(
    const float* __restrict__ kn,
    const float* __restrict__ W2,
    const float* __restrict__ b2)
{
    const int b  = blockIdx.x >> 5;          // 0..3
    const int k0 = (blockIdx.x & 31) * 8;    // 0..248

    __shared__ float knS[8][DKp];            // 8 KB
    const int tid = threadIdx.x;
    for (int i = tid; i < 8 * DKp; i += 256)
        knS[i >> 8][i & 255] = kn[(b * Kp + k0) * DKp + i];
    __syncthreads();

    const int u    = tid & 127;
    const int half = tid >> 7;               // rows half*4 .. half*4+3
    const float bb = b2[u];
    float a0 = bb, a1 = bb, a2 = bb, a3 = bb;
    #pragma unroll 8
    for (int d = 0; d < DKp; d++) {
        const float w = W2[d * UN + u];      // coalesced across threads
        a0 = fmaf(knS[half * 4 + 0][d], w, a0);
        a1 = fmaf(knS[half * 4 + 1][d], w, a1);
        a2 = fmaf(knS[half * 4 + 2][d], w, a2);
        a3 = fmaf(knS[half * 4 + 3][d], w, a3);
    }
    // k = k0 + half*4 + {0..3} is contiguous and 16B aligned -> float4 store
    float4* dst = (float4*)(g_kkT + (size_t)b * UN * Kp + (size_t)u * Kp + k0 + half * 4);
    *dst = make_float4(a0, a1, a2, a3);
}

// ---------------------------------------------------------------------------
// Main fused kernel: e-projection + tanh scores + softmax + context GEMV.
// grid = B * (T/TT) = 256 blocks, 256 threads.
// ---------------------------------------------------------------------------
__global__ void __launch_bounds__(256) attn_main_kernel(
    const float* __restrict__ kn,
    const float* __restrict__ enc,
    const float* __restrict__ W1,
    const float* __restrict__ b1,
    const float* __restrict__ V,
    float* __restrict__ out)
{
    __shared__ float encS[TT][DENC];                 // 8 KB
    __shared__ float eS[TT][UN];                     // 4 KB
    __shared__ float Vs[UN];                         // 0.5 KB
    __shared__ __align__(16) float wT[Kp][TT];       // 8 KB, weights transposed

    const int tid = threadIdx.x;
    const int b   = blockIdx.x >> 6;                 // 0..3
    const int t0  = (blockIdx.x & 63) * TT;          // 0..504

    // Stage encoder rows + V
    for (int i = tid; i < TT * DENC; i += 256)
        encS[i >> 8][i & 255] = enc[(b * Tp + t0) * DENC + i];
    if (tid < UN) Vs[tid] = V[tid];
    __syncthreads();

    // ---- Phase 0: e[tt][u] = enc_row @ W1 + b1 ----
    {
        const int u    = tid & 127;
        const int half = tid >> 7;
        const float bb = b1[u];
        float a0 = bb, a1 = bb, a2 = bb, a3 = bb;
        #pragma unroll 8
        for (int d = 0; d < DENC; d++) {
            const float w = W1[d * UN + u];          // coalesced, L1/L2 resident
            a0 = fmaf(encS[half * 4 + 0][d], w, a0);
            a1 = fmaf(encS[half * 4 + 1][d], w, a1);
            a2 = fmaf(encS[half * 4 + 2][d], w, a2);
            a3 = fmaf(encS[half * 4 + 3][d], w, a3);
        }
        eS[half * 4 + 0][u] = a0;
        eS[half * 4 + 1][u] = a1;
        eS[half * 4 + 2][u] = a2;
        eS[half * 4 + 3][u] = a3;
    }
    __syncthreads();

    // ---- Phase A: scores.  warp = timestep tt, lane owns k = lane + 32*j ----
    const int warp = tid >> 5;
    const int lane = tid & 31;

    float s[8];
    #pragma unroll
    for (int j = 0; j < 8; j++) s[j] = 0.f;

    const float* kkb = g_kkT + (size_t)b * UN * Kp + lane;
    #pragma unroll 2
    for (int u = 0; u < UN; u++) {
        const float e = eS[warp][u];                 // smem broadcast
        const float v = Vs[u];                       // smem broadcast
        const float* row = kkb + u * Kp;             // coalesced across lanes
        #pragma unroll
        for (int j = 0; j < 8; j++) {
            float th;
            const float x = e + row[j * 32];
            asm("tanh.approx.f32 %0, %1;" : "=f"(th) : "f"(x));
            s[j] = fmaf(th, v, s[j]);
        }
    }

    // ---- Softmax over K=256 within the warp (values still in registers) ----
    float mx = s[0];
    #pragma unroll
    for (int j = 1; j < 8; j++) mx = fmaxf(mx, s[j]);
    #pragma unroll
    for (int o = 16; o > 0; o >>= 1) mx = fmaxf(mx, __shfl_xor_sync(0xffffffffu, mx, o));
    float sum = 0.f;
    #pragma unroll
    for (int j = 0; j < 8; j++) { s[j] = __expf(s[j] - mx); sum += s[j]; }
    #pragma unroll
    for (int o = 16; o > 0; o >>= 1) sum += __shfl_xor_sync(0xffffffffu, sum, o);
    const float inv = 1.0f / sum;
    #pragma unroll
    for (int j = 0; j < 8; j++)
        wT[j * 32 + lane][warp] = s[j] * inv;        // transposed for phase C
    __syncthreads();

    // ---- Phase C: context[tt][d] = sum_k w[tt][k] * knowledge[b,k,d] ----
    const int d = tid;                               // 0..255 == DKp
    float acc[TT];
    #pragma unroll
    for (int r = 0; r < TT; r++) acc[r] = 0.f;

    const float* knb = kn + (size_t)b * Kp * DKp + d;
    #pragma unroll 4
    for (int k = 0; k < Kp; k++) {
        const float kv = knb[(size_t)k * DKp];       // coalesced, L2 resident
        const float4 w0 = *(const float4*)&wT[k][0]; // broadcast
        const float4 w1 = *(const float4*)&wT[k][4]; // broadcast
        acc[0] = fmaf(w0.x, kv, acc[0]);
        acc[1] = fmaf(w0.y, kv, acc[1]);
        acc[2] = fmaf(w0.z, kv, acc[2]);
        acc[3] = fmaf(w0.w, kv, acc[3]);
        acc[4] = fmaf(w1.x, kv, acc[4]);
        acc[5] = fmaf(w1.y, kv, acc[5]);
        acc[6] = fmaf(w1.z, kv, acc[6]);
        acc[7] = fmaf(w1.w, kv, acc[7]);
    }
    #pragma unroll
    for (int r = 0; r < TT; r++)
        out[((size_t)(b * Tp + t0 + r)) * DKp + d] = acc[r];
}

// ---------------------------------------------------------------------------
// Harness entry point
// ---------------------------------------------------------------------------
extern "C" void kernel_launch(void* const* d_in, const int* in_sizes, int n_in,
                              void* d_out, int out_size)
{
    const float* kn  = (const float*)d_in[0];  // knowledge_onehot [B,K,D_K]
    const float* enc = (const float*)d_in[1];  // encoder_outputs  [B,T,D_ENC]
    const float* W1  = (const float*)d_in[2];  // [D_ENC,U]
    const float* b1  = (const float*)d_in[3];  // [U]
    const float* W2  = (const float*)d_in[4];  // [D_K,U]
    const float* b2  = (const float*)d_in[5];  // [U]
    const float* V   = (const float*)d_in[6];  // [U,1]
    // d_in[7] = bV: constant shift on scores, softmax-invariant -> ignored.
    float* out = (float*)d_out;                // context [B,T,D_K] fp32

    kk_pre_kernel<<<Bp * (Kp / 8), 256>>>(kn, W2, b2);
    attn_main_kernel<<<Bp * (Tp / TT), 256>>>(kn, enc, W1, b1, V, out);
}

// round 4
// speedup vs baseline: 1.3371x; 1.3371x over previous
#include <cuda_runtime.h>
#include <cstdint>

// Problem constants (fixed by the reference)
#define Bp    4
#define Tp    512
#define Kp    256
#define DENC  256
#define DKp   256
#define UN    128
#define TT    8     // timesteps per block in the main kernel
#define UC    16    // u-rows per kk smem chunk
#define NCHUNK (UN / UC)   // 8

// Scratch: kkT[b][u][k] = (knowledge[b] @ W2 + b2) transposed to [U][K]
__device__ float g_kkT[Bp * UN * Kp];   // 512 KB (L2 resident)

static __device__ __forceinline__ uint32_t smem_u32(const void* p) {
    return (uint32_t)__cvta_generic_to_shared(p);
}
static __device__ __forceinline__ void cp_async16(uint32_t dst, const void* src) {
    asm volatile("cp.async.cg.shared.global [%0], [%1], 16;\n" :: "r"(dst), "l"(src));
}
static __device__ __forceinline__ void cp_commit() {
    asm volatile("cp.async.commit_group;\n");
}
template <int N>
static __device__ __forceinline__ void cp_wait() {
    asm volatile("cp.async.wait_group %0;\n" :: "n"(N));
}

// ---------------------------------------------------------------------------
// Pre-kernel: kkT[b][u][k] = sum_d knowledge[b,k,d] * W2[d,u] + b2[u]
// grid = B * (K/8) = 128 blocks, 256 threads.
// ---------------------------------------------------------------------------
__global__ void __launch_bounds__(256) kk_pre_kernel(
    const float* __restrict__ kn,
    const float* __restrict__ W2,
    const float* __restrict__ b2)
{
    const int b  = blockIdx.x >> 5;          // 0..3
    const int k0 = (blockIdx.x & 31) * 8;    // 0..248

    __shared__ float knS[8][DKp];            // 8 KB
    const int tid = threadIdx.x;
    for (int i = tid; i < 8 * DKp; i += 256)
        knS[i >> 8][i & 255] = kn[(b * Kp + k0) * DKp + i];
    __syncthreads();

    const int u    = tid & 127;
    const int half = tid >> 7;               // rows half*4 .. half*4+3
    const float bb = b2[u];
    float a0 = bb, a1 = bb, a2 = bb, a3 = bb;
    #pragma unroll 8
    for (int d = 0; d < DKp; d++) {
        const float w = W2[d * UN + u];      // coalesced across threads
        a0 = fmaf(knS[half * 4 + 0][d], w, a0);
        a1 = fmaf(knS[half * 4 + 1][d], w, a1);
        a2 = fmaf(knS[half * 4 + 2][d], w, a2);
        a3 = fmaf(knS[half * 4 + 3][d], w, a3);
    }
    float4* dst = (float4*)(g_kkT + (size_t)b * UN * Kp + (size_t)u * Kp + k0 + half * 4);
    *dst = make_float4(a0, a1, a2, a3);
}

// ---------------------------------------------------------------------------
// Main fused kernel: e-projection + tanh scores + softmax + context GEMV,
// with cp.async double-buffered kkT tiles in shared memory.
// grid = B * (T/TT) = 256 blocks, 256 threads.
// ---------------------------------------------------------------------------
__global__ void __launch_bounds__(256) attn_main_kernel(
    const float* __restrict__ kn,
    const float* __restrict__ enc,
    const float* __restrict__ W1,
    const float* __restrict__ b1,
    const float* __restrict__ V,
    float* __restrict__ out)
{
    // encS dead after phase 0; wT born after phase A -> alias them.
    __shared__ union {
        float encS[TT][DENC];                // 8 KB
        float wT[Kp][TT];                    // 8 KB (weights, transposed)
    } uS;
    __shared__ float eS[TT][UN];             // 4 KB
    __shared__ float Vs[UN];                 // 0.5 KB
    __shared__ __align__(16) float kkS[2][UC][Kp];  // 32 KB double buffer

    const int tid = threadIdx.x;
    const int b   = blockIdx.x >> 6;                 // 0..3
    const int t0  = (blockIdx.x & 63) * TT;          // 0..504

    const float* kkb = g_kkT + (size_t)b * UN * Kp;

    // ---- Prefetch kk chunk 0 (overlaps with phase 0 compute) ----
    {
        const float4* src = (const float4*)kkb;      // chunk 0 base
        #pragma unroll
        for (int r = 0; r < 4; r++) {                // 1024 float4 / 256 threads
            const int i = r * 256 + tid;
            cp_async16(smem_u32(&kkS[0][0][0]) + i * 16, src + i);
        }
        cp_commit();
    }

    // Stage encoder rows + V
    for (int i = tid; i < TT * DENC; i += 256)
        uS.encS[i >> 8][i & 255] = enc[(b * Tp + t0) * DENC + i];
    if (tid < UN) Vs[tid] = V[tid];
    __syncthreads();

    // ---- Phase 0: e[tt][u] = enc_row @ W1 + b1 ----
    {
        const int u    = tid & 127;
        const int half = tid >> 7;
        const float bb = b1[u];
        float a0 = bb, a1 = bb, a2 = bb, a3 = bb;
        #pragma unroll 8
        for (int d = 0; d < DENC; d++) {
            const float w = W1[d * UN + u];          // coalesced, L2 resident
            a0 = fmaf(uS.encS[half * 4 + 0][d], w, a0);
            a1 = fmaf(uS.encS[half * 4 + 1][d], w, a1);
            a2 = fmaf(uS.encS[half * 4 + 2][d], w, a2);
            a3 = fmaf(uS.encS[half * 4 + 3][d], w, a3);
        }
        eS[half * 4 + 0][u] = a0;
        eS[half * 4 + 1][u] = a1;
        eS[half * 4 + 2][u] = a2;
        eS[half * 4 + 3][u] = a3;
    }
    __syncthreads();   // encS now dead; wT may be written after this point

    // ---- Phase A: scores. warp = timestep tt, lane owns k = lane + 32*j ----
    const int warp = tid >> 5;
    const int lane = tid & 31;

    float s[8];
    #pragma unroll
    for (int j = 0; j < 8; j++) s[j] = 0.f;

    for (int c = 0; c < NCHUNK; c++) {
        // Prefetch next chunk into the other buffer
        if (c + 1 < NCHUNK) {
            const float4* src = (const float4*)(kkb + (size_t)(c + 1) * UC * Kp);
            uint32_t dstb = smem_u32(&kkS[(c + 1) & 1][0][0]);
            #pragma unroll
            for (int r = 0; r < 4; r++) {
                const int i = r * 256 + tid;
                cp_async16(dstb + i * 16, src + i);
            }
            cp_commit();
            cp_wait<1>();   // current chunk's group complete
        } else {
            cp_wait<0>();
        }
        __syncthreads();    // tile visible to all warps

        const float* tile = &kkS[c & 1][0][0];
        const int ub = c * UC;
        #pragma unroll 4
        for (int u = 0; u < UC; u++) {
            const float e = eS[warp][ub + u];        // smem broadcast
            const float v = Vs[ub + u];              // smem broadcast
            const float* row = tile + u * Kp + lane; // LDS, conflict-free
            #pragma unroll
            for (int j = 0; j < 8; j++) {
                float th;
                const float x = e + row[j * 32];
                asm("tanh.approx.f32 %0, %1;" : "=f"(th) : "f"(x));
                s[j] = fmaf(th, v, s[j]);
            }
        }
        __syncthreads();    // all warps done with this buffer before overwrite
    }

    // ---- Softmax over K=256 within the warp (values in registers) ----
    float mx = s[0];
    #pragma unroll
    for (int j = 1; j < 8; j++) mx = fmaxf(mx, s[j]);
    #pragma unroll
    for (int o = 16; o > 0; o >>= 1) mx = fmaxf(mx, __shfl_xor_sync(0xffffffffu, mx, o));
    float sum = 0.f;
    #pragma unroll
    for (int j = 0; j < 8; j++) { s[j] = __expf(s[j] - mx); sum += s[j]; }
    #pragma unroll
    for (int o = 16; o > 0; o >>= 1) sum += __shfl_xor_sync(0xffffffffu, sum, o);
    const float inv = 1.0f / sum;
    #pragma unroll
    for (int j = 0; j < 8; j++)
        uS.wT[j * 32 + lane][warp] = s[j] * inv;     // transposed for phase C
    __syncthreads();

    // ---- Phase C: context[tt][d] = sum_k w[tt][k] * knowledge[b,k,d] ----
    const int d = tid;                               // 0..255 == DKp
    float acc[TT];
    #pragma unroll
    for (int r = 0; r < TT; r++) acc[r] = 0.f;

    const float* knb = kn + (size_t)b * Kp * DKp + d;
    #pragma unroll 4
    for (int k = 0; k < Kp; k++) {
        const float kv = knb[(size_t)k * DKp];       // coalesced, L2 resident
        const float4 w0 = *(const float4*)&uS.wT[k][0]; // broadcast
        const float4 w1 = *(const float4*)&uS.wT[k][4]; // broadcast
        acc[0] = fmaf(w0.x, kv, acc[0]);
        acc[1] = fmaf(w0.y, kv, acc[1]);
        acc[2] = fmaf(w0.z, kv, acc[2]);
        acc[3] = fmaf(w0.w, kv, acc[3]);
        acc[4] = fmaf(w1.x, kv, acc[4]);
        acc[5] = fmaf(w1.y, kv, acc[5]);
        acc[6] = fmaf(w1.z, kv, acc[6]);
        acc[7] = fmaf(w1.w, kv, acc[7]);
    }
    #pragma unroll
    for (int r = 0; r < TT; r++)
        out[((size_t)(b * Tp + t0 + r)) * DKp + d] = acc[r];
}

// ---------------------------------------------------------------------------
// Harness entry point
// ---------------------------------------------------------------------------
extern "C" void kernel_launch(void* const* d_in, const int* in_sizes, int n_in,
                              void* d_out, int out_size)
{
    const float* kn  = (const float*)d_in[0];  // knowledge_onehot [B,K,D_K]
    const float* enc = (const float*)d_in[1];  // encoder_outputs  [B,T,D_ENC]
    const float* W1  = (const float*)d_in[2];  // [D_ENC,U]
    const float* b1  = (const float*)d_in[3];  // [U]
    const float* W2  = (const float*)d_in[4];  // [D_K,U]
    const float* b2  = (const float*)d_in[5];  // [U]
    const float* V   = (const float*)d_in[6];  // [U,1]
    // d_in[7] = bV: constant shift on scores, softmax-invariant -> ignored.
    float* out = (float*)d_out;                // context [B,T,D_K] fp32

    kk_pre_kernel<<<Bp * (Kp / 8), 256>>>(kn, W2, b2);
    attn_main_kernel<<<Bp * (Tp / TT), 256>>>(kn, enc, W1, b1, V, out);
}